// round 15
// baseline (speedup 1.0000x reference)
#include <cuda_runtime.h>
#include <cstdint>

// Problem constants
#define NN      8192        // N edges
#define EE      256         // embedding dim
#define SS      16          // survival steps
#define NSRC    10000
#define MINDST  10000
#define SURV_ROWS  (SS * NN)            // 131072
#define TOTAL_ROWS (SURV_ROWS + NN)     // 139264 (surv rows + edge rows)

#define BATCH   8                       // rows per stolen work unit
#define NBATCH  (TOTAL_ROWS / BATCH)    // 17408 (exact)
#define PRE_BLOCKS  256                 // 256 x 32 = 8192 edges
#define MAIN_BLOCKS 444                 // 3 blocks/SM x 148 SMs

// Scratch (no allocation allowed -> __device__ globals)
__device__ float  g_td_uv[NN];
__device__ int    g_as[NN];
__device__ int    g_ad[NN];
__device__ float  g_ua[NN];
__device__ int    g_accu_idx[NN];
__device__ double g_bs[NBATCH];          // per-batch surv partial
__device__ double g_bl[NBATCH];          // per-batch lambda partial
__device__ double g_part_acc[MAIN_BLOCKS];
__device__ unsigned int g_next;          // work-steal counter
__device__ unsigned int g_done;          // completion counter

__device__ __forceinline__ float hawkes(float dot, float td,
                                        float b, float psi, float alpha, float w_t)
{
    float g  = dot + b + alpha * expf(-w_t * td * (1.0f / 5000.0f));
    float gp = fminf(fmaxf(g / (psi + 1e-7f), -75.0f), 75.0f);
    return psi * (log1pf(expf(-gp)) + gp);
}

// ---------------------------------------------------------------------------
// Kernel 1 (tiny): resolves indirection chains; resets steal/done counters.
// ---------------------------------------------------------------------------
__global__ __launch_bounds__(32)
void pre_kernel(const int*   __restrict__ assoc,
                const int*   __restrict__ src,
                const int*   __restrict__ dst,
                const float* __restrict__ last_update,
                const float* __restrict__ cur_time,
                const float* __restrict__ last_time_pos)
{
    if (blockIdx.x == 0 && threadIdx.x == 0) { g_next = 0u; g_done = 0u; }

    int e = blockIdx.x * 32 + threadIdx.x;       // always < NN
    int   s   = src[e];
    int   d   = dst[e];
    int   as  = assoc[s];
    int   ad  = assoc[d];
    float lu  = fmaxf(last_update[as], last_update[ad]);
    float ltp = last_time_pos[e];

    g_td_uv[e]    = cur_time[e] - fmaxf(lu, ltp);
    g_as[e]       = as;
    g_ad[e]       = ad;
    g_ua[e]       = (ltp >= lu) ? 1.0f : 0.0f;
    g_accu_idx[e] = s * NSRC + (d - MINDST);
}

// ---------------------------------------------------------------------------
// Kernel 2: persistent streaming kernel, register double-buffer + stealing.
//  - warp-per-row, single-row A/B register buffers (4 float4/lane each):
//    next row's 4 LDG.128 are in flight through the whole reduce/hawkes tail
//  - warps steal 8-row batches via atomicAdd; per-BATCH partials keep the
//    accumulation order input-independent (deterministic across replays)
//  - rows [0, SURV_ROWS): survival rows; [SURV_ROWS, TOTAL): edge rows
//  - threads gtid < NN also hide one random accu gather
//  - last-done block performs the fixed-order final reduction -> out
// ---------------------------------------------------------------------------
__global__ __launch_bounds__(256, 3)
void main_kernel(const float* __restrict__ u,
                 const float* __restrict__ v,
                 const float* __restrict__ tdstep,
                 const float* __restrict__ emb,
                 const float* __restrict__ accu,
                 const float* __restrict__ W,
                 const float* __restrict__ b_,
                 const float* __restrict__ psi_,
                 const float* __restrict__ alpha_,
                 const float* __restrict__ wt_,
                 float* __restrict__ out)
{
    const int tid = threadIdx.x, warp = tid >> 5, lane = tid & 31;

    // W in registers: lane owns float4s {lane, 32+lane} of Wu and
    // {64+lane, 96+lane} of Wv. 4 float4 = 16 regs.
    const float4* w4 = (const float4*)W;
    const float4 wu0 = w4[lane];
    const float4 wu1 = w4[32 + lane];
    const float4 wv0 = w4[64 + lane];
    const float4 wv1 = w4[96 + lane];

    const float b     = b_[0];
    const float psi   = psi_[0];
    const float alpha = alpha_[0];
    const float wt    = wt_[0];

    double acc_a = 0.0;   // use_accu * accu[...] partial (static mapping)
    int gtid = blockIdx.x * 256 + tid;
    if (gtid < NN)
        acc_a = (double)(g_ua[gtid] * __ldg(&accu[g_accu_idx[gtid]]));

    const float4* u4 = (const float4*)u;
    const float4* v4 = (const float4*)v;
    const float4* e4 = (const float4*)emb;

    double bs = 0.0, bl = 0.0;    // current-batch partials (lane 0 accumulates)
    int    bc = -1;               // batch currently being consumed

    // ---- issue stream: batches stolen from g_next --------------------------
    int ib, ioff = 0;
    {
        unsigned int t;
        if (lane == 0) t = atomicAdd(&g_next, 1u);
        t = __shfl_sync(0xffffffffu, t, 0);
        ib = (int)t;
    }

#define NEXT(RV, BV, OK)                                                     \
    do {                                                                     \
        (OK) = false;                                                        \
        if (ib < NBATCH) {                                                   \
            if (ioff == BATCH) {                                             \
                unsigned int _t;                                             \
                if (lane == 0) _t = atomicAdd(&g_next, 1u);                  \
                _t = __shfl_sync(0xffffffffu, _t, 0);                        \
                ib = (int)_t; ioff = 0;                                      \
            }                                                                \
            if (ib < NBATCH) {                                               \
                (RV) = ib * BATCH + ioff; (BV) = ib; ioff++; (OK) = true;    \
            }                                                                \
        }                                                                    \
    } while (0)

#define LOADM(A0, A1, C0, C1, TDU, TD, SV, R)                                \
    do {                                                                     \
        int _r = (R);                                                        \
        (SV) = (_r < SURV_ROWS);                                             \
        const float4 *_pu, *_pv;                                             \
        if (SV) {                                                            \
            _pu = u4 + (size_t)_r * 64;                                      \
            _pv = v4 + (size_t)_r * 64;                                      \
            (TDU) = g_td_uv[_r & (NN - 1)];                                  \
            (TD)  = tdstep[_r] * (TDU);                                      \
        } else {                                                             \
            int _e = _r - SURV_ROWS;                                         \
            _pu = e4 + (size_t)g_as[_e] * 64;                                \
            _pv = e4 + (size_t)g_ad[_e] * 64;                                \
            (TDU) = 0.f;                                                     \
            (TD)  = g_td_uv[_e];                                             \
        }                                                                    \
        (A0) = __ldcs(_pu + lane);                                           \
        (A1) = __ldcs(_pu + 32 + lane);                                      \
        (C0) = __ldcs(_pv + lane);                                           \
        (C1) = __ldcs(_pv + 32 + lane);                                      \
    } while (0)

#define FLUSH(BNEW)                                                          \
    do {                                                                     \
        if ((BNEW) != bc) {                                                  \
            if (lane == 0 && bc >= 0) { g_bs[bc] = bs; g_bl[bc] = bl; }      \
            bs = 0.0; bl = 0.0; bc = (BNEW);                                 \
        }                                                                    \
    } while (0)

#define CONSUME(A0, A1, C0, C1, TDU, TD, SV)                                 \
    do {                                                                     \
        float _d = (A0).x * wu0.x + (A0).y * wu0.y + (A0).z * wu0.z          \
                 + (A0).w * wu0.w                                            \
                 + (A1).x * wu1.x + (A1).y * wu1.y + (A1).z * wu1.z          \
                 + (A1).w * wu1.w                                            \
                 + (C0).x * wv0.x + (C0).y * wv0.y + (C0).z * wv0.z          \
                 + (C0).w * wv0.w                                            \
                 + (C1).x * wv1.x + (C1).y * wv1.y + (C1).z * wv1.z          \
                 + (C1).w * wv1.w;                                           \
        _Pragma("unroll")                                                    \
        for (int _o = 16; _o; _o >>= 1)                                      \
            _d += __shfl_xor_sync(0xffffffffu, _d, _o);                      \
        if (lane == 0) {                                                     \
            float _lam = hawkes(_d, (TD), b, psi, alpha, wt);                \
            if (SV) bs += (double)_lam * (double)(TDU);                      \
            else    bl -= (double)logf(_lam + 1e-7f);                        \
        }                                                                    \
    } while (0)

    // ---- pipeline: A/B single-row register buffers -------------------------
    float4 a0A, a1A, c0A, c1A, a0B, a1B, c0B, c1B;
    float  tduA, tdA, tduB, tdB;
    bool   svA, svB, vA, vB;
    int    bA, bB, rT;

    NEXT(rT, bA, vA); if (vA) LOADM(a0A, a1A, c0A, c1A, tduA, tdA, svA, rT);
    NEXT(rT, bB, vB); if (vB) LOADM(a0B, a1B, c0B, c1B, tduB, tdB, svB, rT);

    for (;;) {
        if (!vA) break;
        FLUSH(bA);
        CONSUME(a0A, a1A, c0A, c1A, tduA, tdA, svA);
        NEXT(rT, bA, vA);
        if (vA) LOADM(a0A, a1A, c0A, c1A, tduA, tdA, svA, rT);

        if (!vB) break;
        FLUSH(bB);
        CONSUME(a0B, a1B, c0B, c1B, tduB, tdB, svB);
        NEXT(rT, bB, vB);
        if (vB) LOADM(a0B, a1B, c0B, c1B, tduB, tdB, svB, rT);
    }
    // drain: at most one buffer pending (A if broke on !vB, B if broke on !vA)
    if (vA)      { FLUSH(bA); CONSUME(a0A, a1A, c0A, c1A, tduA, tdA, svA); }
    else if (vB) { FLUSH(bB); CONSUME(a0B, a1B, c0B, c1B, tduB, tdB, svB); }
    if (lane == 0 && bc >= 0) { g_bs[bc] = bs; g_bl[bc] = bl; }

#undef NEXT
#undef LOADM
#undef FLUSH
#undef CONSUME

    // ---- accu partial: fixed butterfly + fixed block combine ---------------
#pragma unroll
    for (int o = 16; o; o >>= 1)
        acc_a += __shfl_xor_sync(0xffffffffu, acc_a, o);

    __shared__ double sac[8];
    __shared__ int    s_last;
    if (lane == 0) sac[warp] = acc_a;
    __syncthreads();
    if (tid == 0) {
        double q = 0.0;
#pragma unroll
        for (int k = 0; k < 8; k++) q += sac[k];
        g_part_acc[blockIdx.x] = q;
        __threadfence();
        unsigned int prev = atomicAdd(&g_done, 1u);
        s_last = (prev == MAIN_BLOCKS - 1) ? 1 : 0;
    }
    __syncthreads();

    // ---- last block: fixed-order final reduction ---------------------------
    if (s_last) {
        __shared__ double sh[256];

        double s = 0.0;
        for (int j = tid; j < NBATCH; j += 256) s += g_bs[j];
        sh[tid] = s; __syncthreads();
        for (int o = 128; o; o >>= 1) { if (tid < o) sh[tid] += sh[tid + o]; __syncthreads(); }
        double surv = sh[0]; __syncthreads();

        double l = 0.0;
        for (int j = tid; j < NBATCH; j += 256) l += g_bl[j];
        sh[tid] = l; __syncthreads();
        for (int o = 128; o; o >>= 1) { if (tid < o) sh[tid] += sh[tid + o]; __syncthreads(); }
        double lam = sh[0]; __syncthreads();

        double q = 0.0;
        for (int j = tid; j < MAIN_BLOCKS; j += 256) q += g_part_acc[j];
        sh[tid] = q; __syncthreads();
        for (int o = 128; o; o >>= 1) { if (tid < o) sh[tid] += sh[tid + o]; __syncthreads(); }

        if (tid == 0) {
            out[0] = (float)(lam / (double)NN);
            out[1] = (float)((surv / (double)SS + sh[0]) / (double)NN);
        }
    }
}

// ---------------------------------------------------------------------------
// Inputs (metadata order):
//  0 all_embeddings (20000,256) f32   1 assoc (20000,) i32
//  2 src (8192,) i32                  3 pos_dst (8192,) i32
//  4 last_update (20000,) f32         5 cur_time (8192,) f32
//  6 u_non_embeddings (131072,256)    7 v_non_embeddings (131072,256)
//  8 last_time_pos (8192,) f32        9 td_surv_step (16,8192) f32
// 10 event_inten_accu (10000,10000)  11 W_omega (1,512)
// 12 b_omega (1,)  13 psi (1,)  14 alpha (1,)  15 w_t (1,)
// ---------------------------------------------------------------------------
extern "C" void kernel_launch(void* const* d_in, const int* in_sizes, int n_in,
                              void* d_out, int out_size)
{
    const float* emb     = (const float*)d_in[0];
    const int*   assoc   = (const int*)  d_in[1];
    const int*   src     = (const int*)  d_in[2];
    const int*   dst     = (const int*)  d_in[3];
    const float* lupd    = (const float*)d_in[4];
    const float* ctime   = (const float*)d_in[5];
    const float* u_non   = (const float*)d_in[6];
    const float* v_non   = (const float*)d_in[7];
    const float* ltp     = (const float*)d_in[8];
    const float* tdstep  = (const float*)d_in[9];
    const float* accu    = (const float*)d_in[10];
    const float* W       = (const float*)d_in[11];
    const float* b       = (const float*)d_in[12];
    const float* psi     = (const float*)d_in[13];
    const float* alpha   = (const float*)d_in[14];
    const float* w_t     = (const float*)d_in[15];
    float* out = (float*)d_out;

    pre_kernel<<<PRE_BLOCKS, 32>>>(assoc, src, dst, lupd, ctime, ltp);
    main_kernel<<<MAIN_BLOCKS, 256>>>(u_non, v_non, tdstep, emb, accu, W,
                                      b, psi, alpha, w_t, out);
}